// round 9
// baseline (speedup 1.0000x reference)
#include <cuda_runtime.h>
#include <cuda_fp16.h>
#include <stdint.h>

#define B_    4096
#define T_    256
#define D_    64
#define H_    256
#define NBLK  128
#define MTILE 32
#define NTHR  544          // 16 compute warps + 1 producer warp
#define CLUSTER 4

#define S_H   264          // fp32 h row stride (floats)
#define NSTG  3            // weight stage ring depth
#define STGB  24576        // bytes/stage: 16 warps x 6 frags x 32 lanes x 8B
#define SLICE 6144         // per-CTA cooperative slice (STGB/4)
#define QSTEP 52           // k16 stages per timestep: L1(4+16) + L2(16+16)

// Staged gate weights: [q 0..51][w16][t6][lane32] uint2 (k16 B-frag per lane)
__device__ __align__(16) uint2 g_bW[QSTEP * 3072];
// Head weights (tiny, direct-LDG path)
__device__ __align__(16) uint4 g_bF[8 * 8 * 32 + 512];

// SMEM layout (bytes)
#define OFF_WST   0        // 3 x 24576
#define OFF_H16A  73728    // fp16 h1: 2 x 16384
#define OFF_H16B  106496   // fp16 h2: 2 x 16384
#define OFF_X16   139264   // fp16 x : 2 x 4096
#define OFF_SH1   147456   // fp32 h1: 32*264*4 (single buffer, in-place)
#define OFF_SH2   181248
#define OFF_SB1   215040
#define OFF_SB2   219136
#define OFF_SBF   223232
#define OFF_MB    223488   // full[3] @ +0, empty[3] @ +24
#define SMEM_TOT  223552

__device__ __forceinline__ uint32_t pkh(float a, float b) {
    __half2 h = __floats2half2_rn(a, b);
    return *reinterpret_cast<uint32_t*>(&h);
}
__device__ __forceinline__ void mma16(float* d, const uint32_t* a,
                                      uint32_t b0, uint32_t b1) {
    asm volatile(
        "mma.sync.aligned.m16n8k16.row.col.f32.f16.f16.f32 "
        "{%0,%1,%2,%3}, {%4,%5,%6,%7}, {%8,%9}, {%0,%1,%2,%3};\n"
        : "+f"(d[0]), "+f"(d[1]), "+f"(d[2]), "+f"(d[3])
        : "r"(a[0]), "r"(a[1]), "r"(a[2]), "r"(a[3]), "r"(b0), "r"(b1));
}
__device__ __forceinline__ void ldsm4(uint32_t* r, uint32_t addr) {
    asm volatile("ldmatrix.sync.aligned.m8n8.x4.shared.b16 {%0,%1,%2,%3}, [%4];"
                 : "=r"(r[0]), "=r"(r[1]), "=r"(r[2]), "=r"(r[3]) : "r"(addr));
}
__device__ __forceinline__ float ftanh(float x) {
    float y; asm("tanh.approx.f32 %0, %1;" : "=f"(y) : "f"(x)); return y;
}
__device__ __forceinline__ float fsig(float x) {
    return fmaf(0.5f, ftanh(0.5f * x), 0.5f);
}
__device__ __forceinline__ uint32_t cvta_s(const void* p) {
    return (uint32_t)__cvta_generic_to_shared(p);
}
__device__ __forceinline__ uint32_t ctarank() {
    uint32_t r; asm("mov.u32 %0, %%cluster_ctarank;" : "=r"(r)); return r;
}
__device__ __forceinline__ void mbar_init(uint32_t a, uint32_t cnt) {
    asm volatile("mbarrier.init.shared.b64 [%0], %1;" :: "r"(a), "r"(cnt) : "memory");
}
__device__ __forceinline__ void expect_tx(uint32_t a, uint32_t bytes) {
    asm volatile("mbarrier.arrive.expect_tx.shared.b64 _, [%0], %1;"
                 :: "r"(a), "r"(bytes) : "memory");
}
__device__ __forceinline__ void arrive_cluster(uint32_t a, uint32_t rank) {
    asm volatile(
        "{\n\t.reg .b32 ra;\n\t"
        "mapa.shared::cluster.u32 ra, %0, %1;\n\t"
        "mbarrier.arrive.shared::cluster.b64 _, [ra];\n\t}"
        :: "r"(a), "r"(rank) : "memory");
}
__device__ __forceinline__ void wait_parity(uint32_t a, uint32_t par) {
    asm volatile(
        "{\n\t.reg .pred P;\n\t"
        "WL%=:\n\t"
        "mbarrier.try_wait.parity.acquire.cta.shared::cta.b64 P, [%0], %1, 0x989680;\n\t"
        "@P bra.uni WD%=;\n\t"
        "bra.uni WL%=;\n\t"
        "WD%=:\n\t}"
        :: "r"(a), "r"(par) : "memory");
}
__device__ __forceinline__ void wait_parity_rlx(uint32_t a, uint32_t par) {
    asm volatile(
        "{\n\t.reg .pred P;\n\t"
        "WL%=:\n\t"
        "mbarrier.try_wait.parity.relaxed.cta.shared::cta.b64 P, [%0], %1, 0x989680;\n\t"
        "@P bra.uni WD%=;\n\t"
        "bra.uni WL%=;\n\t"
        "WD%=:\n\t}"
        :: "r"(a), "r"(par) : "memory");
}
__device__ __forceinline__ void bulk_mc(uint32_t dst, const void* src,
                                        uint32_t bytes, uint32_t bar,
                                        uint16_t mask) {
    asm volatile(
        "cp.async.bulk.shared::cluster.global.mbarrier::complete_tx::bytes"
        ".multicast::cluster [%0], [%1], %2, [%3], %4;"
        :: "r"(dst), "l"(src), "r"(bytes), "r"(bar), "h"(mask) : "memory");
}

// ---------------------------------------------------------------------------
// Repack gate weights into the staged blob.
// Stage q: q<4: Wih1 (K=64, k0=16q); q<20: Whh1; q<36: Wih2; else Whh2.
__global__ void repack_w(const float* __restrict__ Wih1,
                         const float* __restrict__ Whh1,
                         const float* __restrict__ Wih2,
                         const float* __restrict__ Whh2) {
    int total = QSTEP * 3072;
    for (int o = blockIdx.x * blockDim.x + threadIdx.x; o < total;
         o += gridDim.x * blockDim.x) {
        int lane = o & 31, s2 = o >> 5;
        int t = s2 % 6, s3 = s2 / 6;
        int w = s3 & 15, q = s3 >> 4;
        int G = t >> 1, jt = t & 1, g = lane >> 2, tig = lane & 3;
        int n = G * H_ + w * 16 + jt * 8 + g;
        const float* W; int K, k0;
        if (q < 4)       { W = Wih1; K = 64;  k0 = q * 16; }
        else if (q < 20) { W = Whh1; K = 256; k0 = (q - 4) * 16; }
        else if (q < 36) { W = Wih2; K = 256; k0 = (q - 20) * 16; }
        else             { W = Whh2; K = 256; k0 = (q - 36) * 16; }
        const float* src = W + (size_t)n * K + k0 + 2 * tig;
        uint2 v;
        v.x = pkh(src[0], src[1]);
        v.y = pkh(src[8], src[9]);
        g_bW[o] = v;
    }
}
__global__ void repack_head(const float* __restrict__ W) {
    int total = 8 * 8 * 32;
    for (int o = blockIdx.x * blockDim.x + threadIdx.x; o < total;
         o += gridDim.x * blockDim.x) {
        int lane = o & 31, s = o >> 5;
        int c2 = s & 7, w = s >> 3;
        int g = lane >> 2, tig = lane & 3;
        int n = w * 8 + g;
        const float* src = W + (size_t)n * 256 + c2 * 32 + 2 * tig;
        uint4 v;
        v.x = pkh(src[0],  src[1]);
        v.y = pkh(src[8],  src[9]);
        v.z = pkh(src[16], src[17]);
        v.w = pkh(src[24], src[25]);
        g_bF[o] = v;
    }
}

// ---------------------------------------------------------------------------
struct Cur { uint32_t s, ph; };

// Consume one k16 stage: wait full, ldmatrix A, LDS B, 12 MMAs, broadcast
// empty-arrival to all 4 cluster CTAs, advance cursor.
__device__ __forceinline__ void consume_stage(
    Cur& c, uint32_t stgS, int w, int lane,
    uint32_t a0, uint32_t mstride,
    float (&aR)[2][2][4], float (&aZ)[2][2][4], float (&aN)[2][2][4],
    uint32_t mbF0, uint32_t mbE0) {
    wait_parity(mbF0 + c.s * 8, c.ph);
    uint32_t af0[4], af1[4];
    ldsm4(af0, a0);
    ldsm4(af1, a0 + mstride);
    uint32_t wbase = stgS + c.s * STGB + (uint32_t)w * 1536 + (uint32_t)lane * 8;
#pragma unroll
    for (int t = 0; t < 6; t++) {
        uint32_t w0, w1;
        asm volatile("ld.shared.v2.u32 {%0,%1}, [%2];"
                     : "=r"(w0), "=r"(w1) : "r"(wbase + (uint32_t)t * 256));
        float (*acc)[2][4] = (t < 2) ? aR : (t < 4) ? aZ : aN;
        int jt = t & 1;
        mma16(acc[jt][0], af0, w0, w1);
        mma16(acc[jt][1], af1, w0, w1);
    }
    if (lane == 0) {
        uint32_t ea = mbE0 + c.s * 8;
        arrive_cluster(ea, 0); arrive_cluster(ea, 1);
        arrive_cluster(ea, 2); arrive_cluster(ea, 3);
    }
    if (++c.s == NSTG) { c.s = 0; c.ph ^= 1; }
}

// Head GEMM (warps 0-7): direct LDG of g_bF, K=256.
__device__ __forceinline__ void gemmH(uint32_t ah,
                                      const uint4* __restrict__ blobWL,
                                      int lhi, int sxr, float (&acc)[2][4]) {
    uint4 buf[8];
#pragma unroll
    for (int i = 0; i < 8; i++) buf[i] = blobWL[i * 32];
#pragma unroll 1
    for (int c2 = 0; c2 < 8; c2++) {
        uint32_t af[2][2][4];
#pragma unroll
        for (int m = 0; m < 2; m++)
#pragma unroll
            for (int ch = 0; ch < 2; ch++) {
                int cc = c2 * 4 + ch * 2 + lhi;
                uint32_t addr = (m ? ah + 16 * 512 : ah) +
                                (uint32_t)((cc ^ sxr) << 4);
                ldsm4(af[m][ch], addr);
            }
        uint4 wv = buf[c2];
        mma16(acc[0], af[0][0], wv.x, wv.y);
        mma16(acc[1], af[1][0], wv.x, wv.y);
        mma16(acc[0], af[0][1], wv.z, wv.w);
        mma16(acc[1], af[1][1], wv.z, wv.w);
    }
}

__device__ __forceinline__ void zero4(float (&aR)[2][2][4], float (&aZ)[2][2][4],
                                      float (&aNi)[2][2][4],
                                      float (&aNh)[2][2][4]) {
#pragma unroll
    for (int jt = 0; jt < 2; jt++)
#pragma unroll
        for (int m = 0; m < 2; m++)
#pragma unroll
            for (int q = 0; q < 4; q++) {
                aR[jt][m][q] = 0.f; aZ[jt][m][q] = 0.f;
                aNi[jt][m][q] = 0.f; aNh[jt][m][q] = 0.f;
            }
}

// GRU gate math; fp32 h updated IN PLACE (each thread reads/writes only its
// own cells), fp16 h' written to the next-phase fp16 buffer.
__device__ __forceinline__ void epilogue(float (&aR)[2][2][4], float (&aZ)[2][2][4],
                                         float (&aNi)[2][2][4],
                                         float (&aNh)[2][2][4],
                                         float* h, char* hn16,
                                         const float* __restrict__ sB,
                                         int w, int g, int tig) {
#pragma unroll
    for (int jt = 0; jt < 2; jt++) {
        int j0 = w * 16 + jt * 8 + 2 * tig;
        float br0 = sB[j0],          br1 = sB[j0 + 1];
        float bz0 = sB[H_ + j0],     bz1 = sB[H_ + j0 + 1];
        float bi0 = sB[2 * H_ + j0], bi1 = sB[2 * H_ + j0 + 1];
        float bh0 = sB[3 * H_ + j0], bh1 = sB[3 * H_ + j0 + 1];
        int cc = 2 * w + jt;
#pragma unroll
        for (int m = 0; m < 2; m++)
#pragma unroll
            for (int hq = 0; hq < 2; hq++) {
                int row = g + hq * 8 + m * 16;
                int q0 = hq * 2, q1 = hq * 2 + 1;
                int i0 = row * S_H + j0;
                float hc0 = h[i0], hc1 = h[i0 + 1];
                float r0 = fsig(aR[jt][m][q0] + br0);
                float r1 = fsig(aR[jt][m][q1] + br1);
                float z0 = fsig(aZ[jt][m][q0] + bz0);
                float z1 = fsig(aZ[jt][m][q1] + bz1);
                float n0 = ftanh(aNi[jt][m][q0] + bi0 + r0 * (aNh[jt][m][q0] + bh0));
                float n1 = ftanh(aNi[jt][m][q1] + bi1 + r1 * (aNh[jt][m][q1] + bh1));
                float h0 = (1.f - z0) * n0 + z0 * hc0;
                float h1 = (1.f - z1) * n1 + z1 * hc1;
                float2 v; v.x = h0; v.y = h1;
                *reinterpret_cast<float2*>(h + i0) = v;
                *reinterpret_cast<__half2*>(
                    hn16 + row * 512 + ((cc ^ (row & 7)) << 4) + tig * 4) =
                    __floats2half2_rn(h0, h1);
            }
    }
}

// ---------------------------------------------------------------------------
extern __shared__ __align__(1024) char smem[];

__global__ void __launch_bounds__(NTHR, 1) __cluster_dims__(CLUSTER, 1, 1)
gru_main(const float* __restrict__ x, const float* __restrict__ h1g,
         const float* __restrict__ h2g,
         const float* __restrict__ bih1, const float* __restrict__ bhh1,
         const float* __restrict__ bih2, const float* __restrict__ bhh2,
         const float* __restrict__ bfc, float* __restrict__ out) {
    char*  h16_1 = smem + OFF_H16A;
    char*  h16_2 = smem + OFF_H16B;
    char*  x16   = smem + OFF_X16;
    float* sh1   = (float*)(smem + OFF_SH1);
    float* sh2   = (float*)(smem + OFF_SH2);
    float* sB1   = (float*)(smem + OFF_SB1);
    float* sB2   = (float*)(smem + OFF_SB2);
    float* sBf   = (float*)(smem + OFF_SBF);

    const int tid = threadIdx.x;
    const int w = tid >> 5, lane = tid & 31, g = lane >> 2, tig = lane & 3;
    const int l16 = lane & 15, lhi = lane >> 4, sxr = l16 & 7;
    const int b0 = blockIdx.x * MTILE;
    const uint32_t rank = ctarank();

    const uint32_t mbF0 = cvta_s(smem + OFF_MB);
    const uint32_t mbE0 = mbF0 + 24;
    const uint32_t stgS = cvta_s(smem + OFF_WST);

    if (tid == 0) {
#pragma unroll
        for (int s = 0; s < NSTG; s++) {
            mbar_init(mbF0 + s * 8, 1);
            mbar_init(mbE0 + s * 8, 64);
        }
    }

    if (tid < 256) {
        sB1[tid]          = bih1[tid] + bhh1[tid];
        sB1[H_ + tid]     = bih1[H_ + tid] + bhh1[H_ + tid];
        sB1[2 * H_ + tid] = bih1[2 * H_ + tid];
        sB1[3 * H_ + tid] = bhh1[2 * H_ + tid];
        sB2[tid]          = bih2[tid] + bhh2[tid];
        sB2[H_ + tid]     = bih2[H_ + tid] + bhh2[H_ + tid];
        sB2[2 * H_ + tid] = bih2[2 * H_ + tid];
        sB2[3 * H_ + tid] = bhh2[2 * H_ + tid];
        if (tid < D_) sBf[tid] = bfc[tid];

        int cc = tid >> 3, cb = tid & 7;
        for (int i = 0; i < MTILE; i++) {
            float v1 = h1g[(size_t)(b0 + i) * H_ + tid];
            float v2 = h2g[(size_t)(b0 + i) * H_ + tid];
            sh1[i * S_H + tid] = v1;
            sh2[i * S_H + tid] = v2;
            int off = i * 512 + ((cc ^ (i & 7)) << 4) + cb * 2;
            *reinterpret_cast<__half*>(h16_1 + off) = __float2half_rn(v1);
            *reinterpret_cast<__half*>(h16_2 + off) = __float2half_rn(v2);
        }
    }

    const int xr = (tid & 255) >> 3, xcc = tid & 7;
    const float* xbase = x + ((size_t)(b0 + xr) * T_) * D_ + xcc * 8;
    const int xoff = xr * 128 + ((xcc ^ (xr & 7)) << 4);
    if (tid < 256) {
        float4 v0 = *reinterpret_cast<const float4*>(xbase);
        float4 v1 = *reinterpret_cast<const float4*>(xbase + 4);
        uint4 p;
        p.x = pkh(v0.x, v0.y); p.y = pkh(v0.z, v0.w);
        p.z = pkh(v1.x, v1.y); p.w = pkh(v1.z, v1.w);
        *reinterpret_cast<uint4*>(x16 + xoff) = p;
    }
    __syncthreads();
    // all CTAs' mbarriers initialized before any multicast targets them
    asm volatile("barrier.cluster.arrive.aligned;" ::: "memory");
    asm volatile("barrier.cluster.wait.aligned;" ::: "memory");

    if (w == 16) {
        // ---------------- producer warp ----------------
        uint32_t s = 0, ph = 1;
        uint32_t qq = 0;
        const char* srcb = (const char*)g_bW;
        for (int it = 0; it < T_ * QSTEP; it++) {
            if (lane == 0) {
                wait_parity_rlx(mbE0 + s * 8, ph);
                expect_tx(mbF0 + s * 8, STGB);
                bulk_mc(stgS + s * STGB + rank * SLICE,
                        srcb + (size_t)qq * STGB + rank * SLICE,
                        SLICE, mbF0 + s * 8, (uint16_t)0xF);
            }
            __syncwarp();
            if (++s == NSTG) { s = 0; ph ^= 1; }
            if (++qq == QSTEP) qq = 0;
        }
    } else {
        // ---------------- 16 compute warps ----------------
        const uint32_t u16_1 = cvta_s(h16_1) + l16 * 512;
        const uint32_t u16_2 = cvta_s(h16_2) + l16 * 512;
        const uint32_t ux16  = cvta_s(x16) + l16 * 128;
        const uint4* bF = g_bF + (size_t)(w & 7) * 8 * 32 + lane;

        float aR[2][2][4], aZ[2][2][4], aNi[2][2][4], aNh[2][2][4];
        Cur cur; cur.s = 0; cur.ph = 0;

        for (int t = 0; t < T_; t++) {
            const int cb_ = t & 1;
            uint32_t a_h1c = u16_1 + cb_ * 16384;
            uint32_t a_h1n = u16_1 + (cb_ ^ 1) * 16384;
            uint32_t a_h2c = u16_2 + cb_ * 16384;
            uint32_t a_h2n = u16_2 + (cb_ ^ 1) * 16384;
            uint32_t a_x   = ux16 + cb_ * 4096;
            char* h1n16 = h16_1 + (cb_ ^ 1) * 16384;
            char* h2n16 = h16_2 + (cb_ ^ 1) * 16384;

            asm volatile("bar.sync 1, 512;" ::: "memory");

            float4 vx0, vx1;
            if (tid < 256 && t + 1 < T_) {
                const float* xp = xbase + (size_t)(t + 1) * D_;
                vx0 = *reinterpret_cast<const float4*>(xp);
                vx1 = *reinterpret_cast<const float4*>(xp + 4);
            }

            // ---- Layer 1: stages 0..19 (x-part 4, h-part 16) ----
            zero4(aR, aZ, aNi, aNh);
#pragma unroll 1
            for (int q = 0; q < 20; q++) {
                bool xp = q < 4;
                uint32_t cc = (uint32_t)(xp ? 2 * q : 2 * (q - 4)) + (uint32_t)lhi;
                uint32_t base = xp ? a_x : a_h1c;
                uint32_t mst = xp ? 2048u : 8192u;
                uint32_t a0 = base + ((cc ^ (uint32_t)sxr) << 4);
                consume_stage(cur, stgS, w, lane, a0, mst,
                              aR, aZ, xp ? aNi : aNh, mbF0, mbE0);
            }
            epilogue(aR, aZ, aNi, aNh, sh1, h1n16, sB1, w, g, tig);
            asm volatile("bar.sync 1, 512;" ::: "memory");

            // ---- Layer 2: stages 20..51 (x-part = new h1, 16; h-part 16) ----
            zero4(aR, aZ, aNi, aNh);
#pragma unroll 1
            for (int q = 0; q < 32; q++) {
                bool xp = q < 16;
                uint32_t cc = (uint32_t)(xp ? 2 * q : 2 * (q - 16)) + (uint32_t)lhi;
                uint32_t base = xp ? a_h1n : a_h2c;
                uint32_t a0 = base + ((cc ^ (uint32_t)sxr) << 4);
                consume_stage(cur, stgS, w, lane, a0, 8192u,
                              aR, aZ, xp ? aNi : aNh, mbF0, mbE0);
            }
            epilogue(aR, aZ, aNi, aNh, sh2, h2n16, sB2, w, g, tig);
            asm volatile("bar.sync 1, 512;" ::: "memory");

            // ---- Head (warps 0-7) ----
            if (w < 8) {
                float aF[2][4];
#pragma unroll
                for (int m = 0; m < 2; m++)
#pragma unroll
                    for (int q = 0; q < 4; q++) aF[m][q] = 0.f;
                gemmH(a_h2n, bF, lhi, sxr, aF);
                int d0 = w * 8 + 2 * tig;
                float bs0 = sBf[d0], bs1 = sBf[d0 + 1];
#pragma unroll
                for (int m = 0; m < 2; m++) {
                    int r0 = g + m * 16, r1 = g + 8 + m * 16;
                    float2 v;
                    v.x = aF[m][0] + bs0; v.y = aF[m][1] + bs1;
                    *reinterpret_cast<float2*>(
                        out + ((size_t)(b0 + r0) * T_ + t) * D_ + d0) = v;
                    v.x = aF[m][2] + bs0; v.y = aF[m][3] + bs1;
                    *reinterpret_cast<float2*>(
                        out + ((size_t)(b0 + r1) * T_ + t) * D_ + d0) = v;
                }
            }

            // park x_{t+1}
            if (tid < 256 && t + 1 < T_) {
                uint4 p;
                p.x = pkh(vx0.x, vx0.y); p.y = pkh(vx0.z, vx0.w);
                p.z = pkh(vx1.x, vx1.y); p.w = pkh(vx1.z, vx1.w);
                *reinterpret_cast<uint4*>(x16 + (cb_ ^ 1) * 4096 + xoff) = p;
            }
        }
    }

    __syncthreads();
    // no CTA may exit while peers can still arrive on its barriers
    asm volatile("barrier.cluster.arrive.aligned;" ::: "memory");
    asm volatile("barrier.cluster.wait.aligned;" ::: "memory");

    if (tid < 256) {
        size_t base = (size_t)B_ * T_ * D_;
        for (int i = 0; i < MTILE; i++) {
            out[base + (size_t)(b0 + i) * H_ + tid] = sh1[i * S_H + tid];
            out[base + (size_t)B_ * H_ + (size_t)(b0 + i) * H_ + tid] =
                sh2[i * S_H + tid];
        }
    }
}

// ---------------------------------------------------------------------------
extern "C" void kernel_launch(void* const* d_in, const int* in_sizes, int n_in,
                              void* d_out, int out_size) {
    (void)in_sizes; (void)n_in; (void)out_size;
    const float* x     = (const float*)d_in[0];
    const float* h1    = (const float*)d_in[1];
    const float* h2    = (const float*)d_in[2];
    const float* W_ih1 = (const float*)d_in[3];
    const float* W_hh1 = (const float*)d_in[4];
    const float* b_ih1 = (const float*)d_in[5];
    const float* b_hh1 = (const float*)d_in[6];
    const float* W_ih2 = (const float*)d_in[7];
    const float* W_hh2 = (const float*)d_in[8];
    const float* b_ih2 = (const float*)d_in[9];
    const float* b_hh2 = (const float*)d_in[10];
    const float* W_fc  = (const float*)d_in[11];
    const float* b_fc  = (const float*)d_in[12];
    float* out = (float*)d_out;

    repack_w<<<312, 256>>>(W_ih1, W_hh1, W_ih2, W_hh2);
    repack_head<<<8, 256>>>(W_fc);

    cudaFuncSetAttribute(gru_main, cudaFuncAttributeMaxDynamicSharedMemorySize,
                         SMEM_TOT);

    gru_main<<<NBLK, NTHR, SMEM_TOT>>>(x, h1, h2, b_ih1, b_hh1, b_ih2, b_hh2,
                                       b_fc, out);
}

// round 10
// speedup vs baseline: 1.0779x; 1.0779x over previous
#include <cuda_runtime.h>
#include <cuda_fp16.h>
#include <stdint.h>

#define B_    4096
#define T_    256
#define D_    64
#define H_    256
#define NBLK  128
#define MTILE 32
#define NTHR  544          // 16 compute warps + 1 producer warp
#define CLUSTER 4

#define S_H   264          // fp32 h row stride (floats)
#define NSTG  4            // weight stage ring depth
#define STGB  24576        // bytes/stage: 16 warps x 6 frags x 32 lanes x 8B
#define SLICE 6144         // per-CTA cooperative slice (STGB/4)
#define QSTEP 52           // k16 stages per timestep: L1(4+16) + L2(16+16)

// Staged gate weights: [q 0..51][w16][t6][lane32] uint2 (k16 B-frag per lane)
__device__ __align__(16) uint2 g_bW[QSTEP * 3072];
// Head weights (tiny, direct-LDG path)
__device__ __align__(16) uint4 g_bF[8 * 8 * 32 + 512];

// SMEM layout (bytes)
#define OFF_WST   0        // 4 x 24576 = 98304
#define OFF_H16A  98304    // fp16 h1: 16384 (single buffer, in-place)
#define OFF_H16B  114688   // fp16 h2: 16384
#define OFF_X16   131072   // fp16 x : 4096
#define OFF_SH1   135168   // fp32 h1: 32*264*4 (single buffer, in-place)
#define OFF_SH2   168960
#define OFF_SB1   202752
#define OFF_SB2   206848
#define OFF_SBF   210944
#define OFF_MB    211200   // full[4] @ +0, empty[4] @ +32
#define SMEM_TOT  211264

__device__ __forceinline__ uint32_t pkh(float a, float b) {
    __half2 h = __floats2half2_rn(a, b);
    return *reinterpret_cast<uint32_t*>(&h);
}
__device__ __forceinline__ void mma16(float* d, const uint32_t* a,
                                      uint32_t b0, uint32_t b1) {
    asm volatile(
        "mma.sync.aligned.m16n8k16.row.col.f32.f16.f16.f32 "
        "{%0,%1,%2,%3}, {%4,%5,%6,%7}, {%8,%9}, {%0,%1,%2,%3};\n"
        : "+f"(d[0]), "+f"(d[1]), "+f"(d[2]), "+f"(d[3])
        : "r"(a[0]), "r"(a[1]), "r"(a[2]), "r"(a[3]), "r"(b0), "r"(b1));
}
__device__ __forceinline__ void ldsm4(uint32_t* r, uint32_t addr) {
    asm volatile("ldmatrix.sync.aligned.m8n8.x4.shared.b16 {%0,%1,%2,%3}, [%4];"
                 : "=r"(r[0]), "=r"(r[1]), "=r"(r[2]), "=r"(r[3]) : "r"(addr));
}
__device__ __forceinline__ float ftanh(float x) {
    float y; asm("tanh.approx.f32 %0, %1;" : "=f"(y) : "f"(x)); return y;
}
__device__ __forceinline__ float fsig(float x) {
    return fmaf(0.5f, ftanh(0.5f * x), 0.5f);
}
__device__ __forceinline__ uint32_t cvta_s(const void* p) {
    return (uint32_t)__cvta_generic_to_shared(p);
}
__device__ __forceinline__ uint32_t ctarank() {
    uint32_t r; asm("mov.u32 %0, %%cluster_ctarank;" : "=r"(r)); return r;
}
__device__ __forceinline__ void mbar_init(uint32_t a, uint32_t cnt) {
    asm volatile("mbarrier.init.shared.b64 [%0], %1;" :: "r"(a), "r"(cnt) : "memory");
}
__device__ __forceinline__ void expect_tx(uint32_t a, uint32_t bytes) {
    asm volatile("mbarrier.arrive.expect_tx.shared.b64 _, [%0], %1;"
                 :: "r"(a), "r"(bytes) : "memory");
}
__device__ __forceinline__ void arrive_cluster(uint32_t a, uint32_t rank) {
    asm volatile(
        "{\n\t.reg .b32 ra;\n\t"
        "mapa.shared::cluster.u32 ra, %0, %1;\n\t"
        "mbarrier.arrive.shared::cluster.b64 _, [ra];\n\t}"
        :: "r"(a), "r"(rank) : "memory");
}
__device__ __forceinline__ void wait_parity(uint32_t a, uint32_t par) {
    asm volatile(
        "{\n\t.reg .pred P;\n\t"
        "WL%=:\n\t"
        "mbarrier.try_wait.parity.acquire.cta.shared::cta.b64 P, [%0], %1, 0x989680;\n\t"
        "@P bra.uni WD%=;\n\t"
        "bra.uni WL%=;\n\t"
        "WD%=:\n\t}"
        :: "r"(a), "r"(par) : "memory");
}
__device__ __forceinline__ void wait_parity_rlx(uint32_t a, uint32_t par) {
    asm volatile(
        "{\n\t.reg .pred P;\n\t"
        "WL%=:\n\t"
        "mbarrier.try_wait.parity.relaxed.cta.shared::cta.b64 P, [%0], %1, 0x989680;\n\t"
        "@P bra.uni WD%=;\n\t"
        "bra.uni WL%=;\n\t"
        "WD%=:\n\t}"
        :: "r"(a), "r"(par) : "memory");
}
__device__ __forceinline__ void bulk_mc(uint32_t dst, const void* src,
                                        uint32_t bytes, uint32_t bar,
                                        uint16_t mask) {
    asm volatile(
        "cp.async.bulk.shared::cluster.global.mbarrier::complete_tx::bytes"
        ".multicast::cluster [%0], [%1], %2, [%3], %4;"
        :: "r"(dst), "l"(src), "r"(bytes), "r"(bar), "h"(mask) : "memory");
}

// ---------------------------------------------------------------------------
// Repack gate weights into the staged blob.
// Stage q: q<4: Wih1 (K=64, k0=16q); q<20: Whh1; q<36: Wih2; else Whh2.
__global__ void repack_w(const float* __restrict__ Wih1,
                         const float* __restrict__ Whh1,
                         const float* __restrict__ Wih2,
                         const float* __restrict__ Whh2) {
    int total = QSTEP * 3072;
    for (int o = blockIdx.x * blockDim.x + threadIdx.x; o < total;
         o += gridDim.x * blockDim.x) {
        int lane = o & 31, s2 = o >> 5;
        int t = s2 % 6, s3 = s2 / 6;
        int w = s3 & 15, q = s3 >> 4;
        int G = t >> 1, jt = t & 1, g = lane >> 2, tig = lane & 3;
        int n = G * H_ + w * 16 + jt * 8 + g;
        const float* W; int K, k0;
        if (q < 4)       { W = Wih1; K = 64;  k0 = q * 16; }
        else if (q < 20) { W = Whh1; K = 256; k0 = (q - 4) * 16; }
        else if (q < 36) { W = Wih2; K = 256; k0 = (q - 20) * 16; }
        else             { W = Whh2; K = 256; k0 = (q - 36) * 16; }
        const float* src = W + (size_t)n * K + k0 + 2 * tig;
        uint2 v;
        v.x = pkh(src[0], src[1]);
        v.y = pkh(src[8], src[9]);
        g_bW[o] = v;
    }
}
__global__ void repack_head(const float* __restrict__ W) {
    int total = 8 * 8 * 32;
    for (int o = blockIdx.x * blockDim.x + threadIdx.x; o < total;
         o += gridDim.x * blockDim.x) {
        int lane = o & 31, s = o >> 5;
        int c2 = s & 7, w = s >> 3;
        int g = lane >> 2, tig = lane & 3;
        int n = w * 8 + g;
        const float* src = W + (size_t)n * 256 + c2 * 32 + 2 * tig;
        uint4 v;
        v.x = pkh(src[0],  src[1]);
        v.y = pkh(src[8],  src[9]);
        v.z = pkh(src[16], src[17]);
        v.w = pkh(src[24], src[25]);
        g_bF[o] = v;
    }
}

// ---------------------------------------------------------------------------
struct Cur { uint32_t s, ph; };

// Consume one k16 stage: wait full, ldmatrix A, LDS B, 12 MMAs, broadcast
// empty-arrival to all 4 cluster CTAs, advance cursor.
__device__ __forceinline__ void consume_stage(
    Cur& c, uint32_t stgS, int w, int lane,
    uint32_t a0, uint32_t mstride,
    float (&aR)[2][2][4], float (&aZ)[2][2][4], float (&aN)[2][2][4],
    uint32_t mbF0, uint32_t mbE0) {
    wait_parity(mbF0 + c.s * 8, c.ph);
    uint32_t af0[4], af1[4];
    ldsm4(af0, a0);
    ldsm4(af1, a0 + mstride);
    uint32_t wbase = stgS + c.s * STGB + (uint32_t)w * 1536 + (uint32_t)lane * 8;
    uint32_t wv[6][2];
#pragma unroll
    for (int t = 0; t < 6; t++)
        asm volatile("ld.shared.v2.u32 {%0,%1}, [%2];"
                     : "=r"(wv[t][0]), "=r"(wv[t][1])
                     : "r"(wbase + (uint32_t)t * 256));
#pragma unroll
    for (int t = 0; t < 6; t++) {
        float (*acc)[2][4] = (t < 2) ? aR : (t < 4) ? aZ : aN;
        int jt = t & 1;
        mma16(acc[jt][0], af0, wv[t][0], wv[t][1]);
        mma16(acc[jt][1], af1, wv[t][0], wv[t][1]);
    }
    if (lane == 0) {
        uint32_t ea = mbE0 + c.s * 8;
        arrive_cluster(ea, 0); arrive_cluster(ea, 1);
        arrive_cluster(ea, 2); arrive_cluster(ea, 3);
    }
    if (++c.s == NSTG) { c.s = 0; c.ph ^= 1; }
}

// Head GEMM (warps 0-7): direct LDG of g_bF, K=256.
__device__ __forceinline__ void gemmH(uint32_t ah,
                                      const uint4* __restrict__ blobWL,
                                      int lhi, int sxr, float (&acc)[2][4]) {
    uint4 buf[8];
#pragma unroll
    for (int i = 0; i < 8; i++) buf[i] = blobWL[i * 32];
#pragma unroll 1
    for (int c2 = 0; c2 < 8; c2++) {
        uint32_t af[2][2][4];
#pragma unroll
        for (int m = 0; m < 2; m++)
#pragma unroll
            for (int ch = 0; ch < 2; ch++) {
                int cc = c2 * 4 + ch * 2 + lhi;
                uint32_t addr = (m ? ah + 16 * 512 : ah) +
                                (uint32_t)((cc ^ sxr) << 4);
                ldsm4(af[m][ch], addr);
            }
        uint4 wv = buf[c2];
        mma16(acc[0], af[0][0], wv.x, wv.y);
        mma16(acc[1], af[1][0], wv.x, wv.y);
        mma16(acc[0], af[0][1], wv.z, wv.w);
        mma16(acc[1], af[1][1], wv.z, wv.w);
    }
}

__device__ __forceinline__ void zero4(float (&aR)[2][2][4], float (&aZ)[2][2][4],
                                      float (&aNi)[2][2][4],
                                      float (&aNh)[2][2][4]) {
#pragma unroll
    for (int jt = 0; jt < 2; jt++)
#pragma unroll
        for (int m = 0; m < 2; m++)
#pragma unroll
            for (int q = 0; q < 4; q++) {
                aR[jt][m][q] = 0.f; aZ[jt][m][q] = 0.f;
                aNi[jt][m][q] = 0.f; aNh[jt][m][q] = 0.f;
            }
}

// GRU gate math; fp32 h updated IN PLACE (each thread touches only its own
// cells), fp16 h' written IN PLACE (callers provide barriers around it).
__device__ __forceinline__ void epilogue(float (&aR)[2][2][4], float (&aZ)[2][2][4],
                                         float (&aNi)[2][2][4],
                                         float (&aNh)[2][2][4],
                                         float* h, char* h16,
                                         const float* __restrict__ sB,
                                         int w, int g, int tig) {
#pragma unroll
    for (int jt = 0; jt < 2; jt++) {
        int j0 = w * 16 + jt * 8 + 2 * tig;
        float br0 = sB[j0],          br1 = sB[j0 + 1];
        float bz0 = sB[H_ + j0],     bz1 = sB[H_ + j0 + 1];
        float bi0 = sB[2 * H_ + j0], bi1 = sB[2 * H_ + j0 + 1];
        float bh0 = sB[3 * H_ + j0], bh1 = sB[3 * H_ + j0 + 1];
        int cc = 2 * w + jt;
#pragma unroll
        for (int m = 0; m < 2; m++)
#pragma unroll
            for (int hq = 0; hq < 2; hq++) {
                int row = g + hq * 8 + m * 16;
                int q0 = hq * 2, q1 = hq * 2 + 1;
                int i0 = row * S_H + j0;
                float hc0 = h[i0], hc1 = h[i0 + 1];
                float r0 = fsig(aR[jt][m][q0] + br0);
                float r1 = fsig(aR[jt][m][q1] + br1);
                float z0 = fsig(aZ[jt][m][q0] + bz0);
                float z1 = fsig(aZ[jt][m][q1] + bz1);
                float n0 = ftanh(aNi[jt][m][q0] + bi0 + r0 * (aNh[jt][m][q0] + bh0));
                float n1 = ftanh(aNi[jt][m][q1] + bi1 + r1 * (aNh[jt][m][q1] + bh1));
                float h0 = (1.f - z0) * n0 + z0 * hc0;
                float h1 = (1.f - z1) * n1 + z1 * hc1;
                float2 v; v.x = h0; v.y = h1;
                *reinterpret_cast<float2*>(h + i0) = v;
                *reinterpret_cast<__half2*>(
                    h16 + row * 512 + ((cc ^ (row & 7)) << 4) + tig * 4) =
                    __floats2half2_rn(h0, h1);
            }
    }
}

// ---------------------------------------------------------------------------
extern __shared__ __align__(1024) char smem[];

__global__ void __launch_bounds__(NTHR, 1) __cluster_dims__(CLUSTER, 1, 1)
gru_main(const float* __restrict__ x, const float* __restrict__ h1g,
         const float* __restrict__ h2g,
         const float* __restrict__ bih1, const float* __restrict__ bhh1,
         const float* __restrict__ bih2, const float* __restrict__ bhh2,
         const float* __restrict__ bfc, float* __restrict__ out) {
    char*  h16_1 = smem + OFF_H16A;
    char*  h16_2 = smem + OFF_H16B;
    char*  x16   = smem + OFF_X16;
    float* sh1   = (float*)(smem + OFF_SH1);
    float* sh2   = (float*)(smem + OFF_SH2);
    float* sB1   = (float*)(smem + OFF_SB1);
    float* sB2   = (float*)(smem + OFF_SB2);
    float* sBf   = (float*)(smem + OFF_SBF);

    const int tid = threadIdx.x;
    const int w = tid >> 5, lane = tid & 31, g = lane >> 2, tig = lane & 3;
    const int l16 = lane & 15, lhi = lane >> 4, sxr = l16 & 7;
    const int b0 = blockIdx.x * MTILE;
    const uint32_t rank = ctarank();

    const uint32_t mbF0 = cvta_s(smem + OFF_MB);
    const uint32_t mbE0 = mbF0 + NSTG * 8;
    const uint32_t stgS = cvta_s(smem + OFF_WST);

    if (tid == 0) {
#pragma unroll
        for (int s = 0; s < NSTG; s++) {
            mbar_init(mbF0 + s * 8, 1);
            mbar_init(mbE0 + s * 8, 64);
        }
    }

    if (tid < 256) {
        sB1[tid]          = bih1[tid] + bhh1[tid];
        sB1[H_ + tid]     = bih1[H_ + tid] + bhh1[H_ + tid];
        sB1[2 * H_ + tid] = bih1[2 * H_ + tid];
        sB1[3 * H_ + tid] = bhh1[2 * H_ + tid];
        sB2[tid]          = bih2[tid] + bhh2[tid];
        sB2[H_ + tid]     = bih2[H_ + tid] + bhh2[H_ + tid];
        sB2[2 * H_ + tid] = bih2[2 * H_ + tid];
        sB2[3 * H_ + tid] = bhh2[2 * H_ + tid];
        if (tid < D_) sBf[tid] = bfc[tid];

        int cc = tid >> 3, cb = tid & 7;
        for (int i = 0; i < MTILE; i++) {
            float v1 = h1g[(size_t)(b0 + i) * H_ + tid];
            float v2 = h2g[(size_t)(b0 + i) * H_ + tid];
            sh1[i * S_H + tid] = v1;
            sh2[i * S_H + tid] = v2;
            int off = i * 512 + ((cc ^ (i & 7)) << 4) + cb * 2;
            *reinterpret_cast<__half*>(h16_1 + off) = __float2half_rn(v1);
            *reinterpret_cast<__half*>(h16_2 + off) = __float2half_rn(v2);
        }
    }

    const int xr = (tid & 255) >> 3, xcc = tid & 7;
    const float* xbase = x + ((size_t)(b0 + xr) * T_) * D_ + xcc * 8;
    const int xoff = xr * 128 + ((xcc ^ (xr & 7)) << 4);
    if (tid < 256) {
        float4 v0 = *reinterpret_cast<const float4*>(xbase);
        float4 v1 = *reinterpret_cast<const float4*>(xbase + 4);
        uint4 p;
        p.x = pkh(v0.x, v0.y); p.y = pkh(v0.z, v0.w);
        p.z = pkh(v1.x, v1.y); p.w = pkh(v1.z, v1.w);
        *reinterpret_cast<uint4*>(x16 + xoff) = p;
    }
    __syncthreads();
    // all CTAs' mbarriers initialized before any multicast targets them
    asm volatile("barrier.cluster.arrive.aligned;" ::: "memory");
    asm volatile("barrier.cluster.wait.aligned;" ::: "memory");

    if (w == 16) {
        // ---------------- producer warp ----------------
        uint32_t s = 0, ph = 1;
        uint32_t qq = 0;
        const char* srcb = (const char*)g_bW;
        for (int it = 0; it < T_ * QSTEP; it++) {
            if (lane == 0) {
                wait_parity_rlx(mbE0 + s * 8, ph);
                expect_tx(mbF0 + s * 8, STGB);
                bulk_mc(stgS + s * STGB + rank * SLICE,
                        srcb + (size_t)qq * STGB + rank * SLICE,
                        SLICE, mbF0 + s * 8, (uint16_t)0xF);
            }
            __syncwarp();
            if (++s == NSTG) { s = 0; ph ^= 1; }
            if (++qq == QSTEP) qq = 0;
        }
    } else {
        // ---------------- 16 compute warps ----------------
        const uint32_t a_h1 = cvta_s(h16_1) + l16 * 512;
        const uint32_t a_h2 = cvta_s(h16_2) + l16 * 512;
        const uint32_t a_x  = cvta_s(x16) + l16 * 128;
        const uint4* bF = g_bF + (size_t)(w & 7) * 8 * 32 + lane;

        float aR[2][2][4], aZ[2][2][4], aNi[2][2][4], aNh[2][2][4];
        Cur cur; cur.s = 0; cur.ph = 0;

        for (int t = 0; t < T_; t++) {
            // issue x_{t+1} loads early (DRAM latency hidden behind L1 gemm)
            float4 vx0, vx1;
            if (tid < 256 && t + 1 < T_) {
                const float* xp = xbase + (size_t)(t + 1) * D_;
                vx0 = *reinterpret_cast<const float4*>(xp);
                vx1 = *reinterpret_cast<const float4*>(xp + 4);
            }

            // ---- Layer 1 gemm: stages 0..19 (x-part 4, h-part 16) ----
            zero4(aR, aZ, aNi, aNh);
#pragma unroll 1
            for (int q = 0; q < 20; q++) {
                bool xp = q < 4;
                uint32_t cc = (uint32_t)(xp ? 2 * q : 2 * (q - 4)) + (uint32_t)lhi;
                uint32_t base = xp ? a_x : a_h1;
                uint32_t mst = xp ? 2048u : 8192u;
                uint32_t a0 = base + ((cc ^ (uint32_t)sxr) << 4);
                consume_stage(cur, stgS, w, lane, a0, mst,
                              aR, aZ, xp ? aNi : aNh, mbF0, mbE0);
            }
            asm volatile("bar.sync 1, 512;" ::: "memory");  // reads done
            // park x_{t+1} (x16 free now) + L1 epilogue (in-place)
            if (tid < 256 && t + 1 < T_) {
                uint4 p;
                p.x = pkh(vx0.x, vx0.y); p.y = pkh(vx0.z, vx0.w);
                p.z = pkh(vx1.x, vx1.y); p.w = pkh(vx1.z, vx1.w);
                *reinterpret_cast<uint4*>(x16 + xoff) = p;
            }
            epilogue(aR, aZ, aNi, aNh, sh1, h16_1, sB1, w, g, tig);
            asm volatile("bar.sync 1, 512;" ::: "memory");  // h1_16 visible

            // ---- Layer 2 gemm: stages 20..51 ----
            zero4(aR, aZ, aNi, aNh);
#pragma unroll 1
            for (int q = 0; q < 32; q++) {
                bool xp = q < 16;
                uint32_t cc = (uint32_t)(xp ? 2 * q : 2 * (q - 16)) + (uint32_t)lhi;
                uint32_t base = xp ? a_h1 : a_h2;
                uint32_t a0 = base + ((cc ^ (uint32_t)sxr) << 4);
                consume_stage(cur, stgS, w, lane, a0, 8192u,
                              aR, aZ, xp ? aNi : aNh, mbF0, mbE0);
            }
            asm volatile("bar.sync 1, 512;" ::: "memory");  // h2_16 reads done
            epilogue(aR, aZ, aNi, aNh, sh2, h16_2, sB2, w, g, tig);
            asm volatile("bar.sync 1, 512;" ::: "memory");  // h2_16 visible

            // ---- Head (warps 0-7); warps 8-15 flow into next step ----
            if (w < 8) {
                float aF[2][4];
#pragma unroll
                for (int m = 0; m < 2; m++)
#pragma unroll
                    for (int q = 0; q < 4; q++) aF[m][q] = 0.f;
                gemmH(a_h2, bF, lhi, sxr, aF);
                int d0 = w * 8 + 2 * tig;
                float bs0 = sBf[d0], bs1 = sBf[d0 + 1];
#pragma unroll
                for (int m = 0; m < 2; m++) {
                    int r0 = g + m * 16, r1 = g + 8 + m * 16;
                    float2 v;
                    v.x = aF[m][0] + bs0; v.y = aF[m][1] + bs1;
                    *reinterpret_cast<float2*>(
                        out + ((size_t)(b0 + r0) * T_ + t) * D_ + d0) = v;
                    v.x = aF[m][2] + bs0; v.y = aF[m][3] + bs1;
                    *reinterpret_cast<float2*>(
                        out + ((size_t)(b0 + r1) * T_ + t) * D_ + d0) = v;
                }
            }
        }
    }

    __syncthreads();
    // no CTA may exit while peers can still arrive on its barriers
    asm volatile("barrier.cluster.arrive.aligned;" ::: "memory");
    asm volatile("barrier.cluster.wait.aligned;" ::: "memory");

    if (tid < 256) {
        size_t base = (size_t)B_ * T_ * D_;
        for (int i = 0; i < MTILE; i++) {
            out[base + (size_t)(b0 + i) * H_ + tid] = sh1[i * S_H + tid];
            out[base + (size_t)B_ * H_ + (size_t)(b0 + i) * H_ + tid] =
                sh2[i * S_H + tid];
        }
    }
}

// ---------------------------------------------------------------------------
extern "C" void kernel_launch(void* const* d_in, const int* in_sizes, int n_in,
                              void* d_out, int out_size) {
    (void)in_sizes; (void)n_in; (void)out_size;
    const float* x     = (const float*)d_in[0];
    const float* h1    = (const float*)d_in[1];
    const float* h2    = (const float*)d_in[2];
    const float* W_ih1 = (const float*)d_in[3];
    const float* W_hh1 = (const float*)d_in[4];
    const float* b_ih1 = (const float*)d_in[5];
    const float* b_hh1 = (const float*)d_in[6];
    const float* W_ih2 = (const float*)d_in[7];
    const float* W_hh2 = (const float*)d_in[8];
    const float* b_ih2 = (const float*)d_in[9];
    const float* b_hh2 = (const float*)d_in[10];
    const float* W_fc  = (const float*)d_in[11];
    const float* b_fc  = (const float*)d_in[12];
    float* out = (float*)d_out;

    repack_w<<<312, 256>>>(W_ih1, W_hh1, W_ih2, W_hh2);
    repack_head<<<8, 256>>>(W_fc);

    cudaFuncSetAttribute(gru_main, cudaFuncAttributeMaxDynamicSharedMemorySize,
                         SMEM_TOT);

    gru_main<<<NBLK, NTHR, SMEM_TOT>>>(x, h1, h2, b_ih1, b_hh1, b_ih2, b_hh2,
                                       b_fc, out);
}